// round 2
// baseline (speedup 1.0000x reference)
#include <cuda_runtime.h>
#include <math.h>
#include <stdint.h>

// Problem constants
#define BQ 16
#define LQ 2048
#define EQ 1280
#define VQ 32
#define PQ 496
#define NROWS (BQ * LQ)        // 32768
#define N2 (VQ + PQ)           // 528
#define LN_EPS 1e-12f

// Scratch (device globals: no allocation allowed in kernel_launch)
__device__ float g_h[(size_t)NROWS * EQ];     // post-GELU / post-LN hidden
__device__ float g_l2[(size_t)NROWS * N2];    // [pi_logits | Theta_raw]
__device__ float g_w2[(size_t)EQ * N2];       // packed [theta_w | Theta_w]
__device__ float g_b2[N2];

// ---------------------------------------------------------------------------
// Pack theta_w (E,V) and Theta_w (E,P) into one (E, 528) matrix + bias
// ---------------------------------------------------------------------------
__global__ void pack_w2_kernel(const float* __restrict__ tw,
                               const float* __restrict__ tb,
                               const float* __restrict__ Tw,
                               const float* __restrict__ Tb) {
    int idx = blockIdx.x * blockDim.x + threadIdx.x;
    int total = EQ * N2;
    if (idx < total) {
        int k = idx / N2;
        int j = idx - k * N2;
        g_w2[idx] = (j < VQ) ? tw[k * VQ + j] : Tw[k * PQ + (j - VQ)];
    }
    if (idx < N2) g_b2[idx] = (idx < VQ) ? tb[idx] : Tb[idx - VQ];
}

// ---------------------------------------------------------------------------
// SGEMM: C = op(A @ B + bias), A: MxK row-major, B: KxN row-major
// 128x128 tile, K-step 8, 256 threads, 8x8 per-thread microtile.
// GELU template flag fuses exact-erf gelu into epilogue.
// ---------------------------------------------------------------------------
template <bool GELU>
__global__ void __launch_bounds__(256, 2)
sgemm_kernel(const float* __restrict__ A, const float* __restrict__ B,
             const float* __restrict__ bias, float* __restrict__ C,
             int M, int N, int K) {
    __shared__ float As[8][128];
    __shared__ float Bs[8][128];

    int tid = threadIdx.x;
    int m0 = blockIdx.y * 128;
    int n0 = blockIdx.x * 128;

    int ar = tid >> 1;             // 0..127 (A row within tile)
    int ak = (tid & 1) << 2;       // 0 or 4 (k offset)
    int bk = tid >> 5;             // 0..7   (B k-row within tile)
    int bc = (tid & 31) << 2;      // 0..124 (B col within tile)

    int row0 = (tid >> 4) << 3;    // microtile row base
    int col0 = (tid & 15) << 3;    // microtile col base

    float acc[8][8];
#pragma unroll
    for (int i = 0; i < 8; i++)
#pragma unroll
        for (int j = 0; j < 8; j++) acc[i][j] = 0.0f;

    const float* Aptr = A + (size_t)(m0 + ar) * K + ak;
    const float* Bptr = B + (size_t)bk * N + n0 + bc;
    bool bload = (n0 + bc) < N;

    for (int k0 = 0; k0 < K; k0 += 8) {
        float4 av = *(const float4*)(Aptr + k0);
        As[ak + 0][ar] = av.x;
        As[ak + 1][ar] = av.y;
        As[ak + 2][ar] = av.z;
        As[ak + 3][ar] = av.w;

        float4 bv = make_float4(0.f, 0.f, 0.f, 0.f);
        if (bload) bv = *(const float4*)(Bptr + (size_t)k0 * N);
        *(float4*)&Bs[bk][bc] = bv;

        __syncthreads();

#pragma unroll
        for (int kk = 0; kk < 8; kk++) {
            float a[8], b[8];
            *(float4*)(a)     = *(const float4*)&As[kk][row0];
            *(float4*)(a + 4) = *(const float4*)&As[kk][row0 + 4];
            *(float4*)(b)     = *(const float4*)&Bs[kk][col0];
            *(float4*)(b + 4) = *(const float4*)&Bs[kk][col0 + 4];
#pragma unroll
            for (int i = 0; i < 8; i++)
#pragma unroll
                for (int j = 0; j < 8; j++)
                    acc[i][j] = fmaf(a[i], b[j], acc[i][j]);
        }
        __syncthreads();
    }

    // Epilogue: bias (+ optional exact GELU), vectorized stores
#pragma unroll
    for (int i = 0; i < 8; i++) {
        size_t m = (size_t)(m0 + row0 + i);
#pragma unroll
        for (int j = 0; j < 8; j += 4) {
            int n = n0 + col0 + j;
            if (n < N) {
                float4 o;
                float v0 = acc[i][j + 0] + bias[n + 0];
                float v1 = acc[i][j + 1] + bias[n + 1];
                float v2 = acc[i][j + 2] + bias[n + 2];
                float v3 = acc[i][j + 3] + bias[n + 3];
                if (GELU) {
                    v0 = 0.5f * v0 * (1.0f + erff(v0 * 0.70710678118654752f));
                    v1 = 0.5f * v1 * (1.0f + erff(v1 * 0.70710678118654752f));
                    v2 = 0.5f * v2 * (1.0f + erff(v2 * 0.70710678118654752f));
                    v3 = 0.5f * v3 * (1.0f + erff(v3 * 0.70710678118654752f));
                }
                o.x = v0; o.y = v1; o.z = v2; o.w = v3;
                *(float4*)&C[m * N + n] = o;
            }
        }
    }
}

// ---------------------------------------------------------------------------
// Row LayerNorm over E=1280, one block (256 thr) per row, in-place
// ---------------------------------------------------------------------------
__device__ __forceinline__ float block_reduce_sum(float v) {
    __shared__ float sh[8];
#pragma unroll
    for (int o = 16; o > 0; o >>= 1) v += __shfl_xor_sync(0xffffffffu, v, o);
    int lane = threadIdx.x & 31, wid = threadIdx.x >> 5;
    if (lane == 0) sh[wid] = v;
    __syncthreads();
    v = (lane < 8) ? sh[lane] : 0.0f;
#pragma unroll
    for (int o = 4; o > 0; o >>= 1) v += __shfl_xor_sync(0xffffffffu, v, o);
    v = __shfl_sync(0xffffffffu, v, 0);
    __syncthreads();  // protect sh[] for next call
    return v;
}

__global__ void ln_kernel(float* __restrict__ h, const float* __restrict__ g,
                          const float* __restrict__ b) {
    size_t r = blockIdx.x;
    float* row = h + r * EQ;
    int t = threadIdx.x;

    float x[5];
    float s = 0.0f;
#pragma unroll
    for (int i = 0; i < 5; i++) {
        x[i] = row[t + i * 256];
        s += x[i];
    }
    float mu = block_reduce_sum(s) * (1.0f / EQ);

    float v = 0.0f;
#pragma unroll
    for (int i = 0; i < 5; i++) {
        float d = x[i] - mu;
        v += d * d;
    }
    float var = block_reduce_sum(v) * (1.0f / EQ);
    float inv = rsqrtf(var + LN_EPS);

#pragma unroll
    for (int i = 0; i < 5; i++) {
        int c = t + i * 256;
        row[c] = (x[i] - mu) * inv * g[c] + b[c];
    }
}

// ---------------------------------------------------------------------------
// Finalize: per row -> masked log-softmax(V=32), softplus(496), build Q(32x32)
// One warp per row, 8 rows per block.
// Mask is read as int32 words: any nonzero 32-bit word == "true". This is
// robust to int32 {0,1}, float32 {0.0,1.0}, and byte-packed encodings.
// ---------------------------------------------------------------------------
__global__ void __launch_bounds__(256)
finalize_kernel(const int* __restrict__ mask32,
                float* __restrict__ qOut, float* __restrict__ piOut) {
    __shared__ float th[8][512];    // softplus'd Theta per warp (496 used)
    __shared__ float psq[8][32];    // sqrt(pi) (1.0 where masked)
    __shared__ float mf[32];        // mask as float, shared across warps

    int lane = threadIdx.x;         // 0..31
    int w = threadIdx.y;            // 0..7
    size_t r = (size_t)blockIdx.x * 8 + w;

    if (w == 0) mf[lane] = (mask32[lane] != 0) ? 1.0f : 0.0f;
    __syncthreads();

    const float* base = g_l2 + r * N2;

    // masked log-softmax over V=32 (one lane per vocab entry)
    bool mk = mf[lane] > 0.5f;
    float x = base[lane];
    float xm = mk ? x : -INFINITY;
    float mx = xm;
#pragma unroll
    for (int o = 16; o > 0; o >>= 1) mx = fmaxf(mx, __shfl_xor_sync(0xffffffffu, mx, o));
    float e = mk ? expf(xm - mx) : 0.0f;
    float ssum = e;
#pragma unroll
    for (int o = 16; o > 0; o >>= 1) ssum += __shfl_xor_sync(0xffffffffu, ssum, o);

    if (piOut) piOut[r * VQ + lane] = e / ssum;
    float logpi = xm - mx - logf(ssum);
    psq[w][lane] = mk ? expf(0.5f * logpi) : 1.0f;

    // softplus of the 496 upper-tri raw rates
    for (int idx = lane; idx < PQ; idx += 32) {
        float t = base[VQ + idx];
        th[w][idx] = fmaxf(t, 0.0f) + log1pf(expf(-fabsf(t)));
    }
    __syncwarp();

    // lane i owns Q row i
    int i = lane;
    float mi = mf[i];
    float inv = 1.0f / psq[w][i];
    float q[32];
    float rs = 0.0f;
#pragma unroll
    for (int j = 0; j < 32; j++) {
        float val = 0.0f;
        if (j != i) {
            int lo = min(i, j), hi = max(i, j);
            int idx = lo * VQ - (lo * (lo + 1)) / 2 + (hi - lo - 1);
            val = th[w][idx] * mi * mf[j] * psq[w][j] * inv;
        }
        q[j] = val;
        rs += val;
    }
#pragma unroll
    for (int j = 0; j < 32; j++)
        if (j == i) q[j] = -rs;

    float* out = qOut + r * (VQ * VQ) + (size_t)i * VQ;
#pragma unroll
    for (int j = 0; j < 32; j += 4)
        *(float4*)(out + j) = make_float4(q[j], q[j + 1], q[j + 2], q[j + 3]);
}

// ---------------------------------------------------------------------------
extern "C" void kernel_launch(void* const* d_in, const int* in_sizes, int n_in,
                              void* d_out, int out_size) {
    const float* hx      = (const float*)d_in[0];
    const int*   vmask   = (const int*)d_in[1];
    const float* dense_w = (const float*)d_in[2];
    const float* dense_b = (const float*)d_in[3];
    const float* ln_g    = (const float*)d_in[4];
    const float* ln_b    = (const float*)d_in[5];
    const float* theta_w = (const float*)d_in[6];
    const float* theta_b = (const float*)d_in[7];
    const float* Theta_w = (const float*)d_in[8];
    const float* Theta_b = (const float*)d_in[9];

    float *hptr, *l2ptr, *w2ptr, *b2ptr;
    cudaGetSymbolAddress((void**)&hptr, g_h);
    cudaGetSymbolAddress((void**)&l2ptr, g_l2);
    cudaGetSymbolAddress((void**)&w2ptr, g_w2);
    cudaGetSymbolAddress((void**)&b2ptr, g_b2);

    // output layout: Q (B,L,V,V) then pi (B,L,V), fp32
    const size_t Q_ELEMS = (size_t)NROWS * VQ * VQ;
    const size_t PI_ELEMS = (size_t)NROWS * VQ;
    float* qOut = (float*)d_out;
    float* piOut = ((size_t)out_size >= Q_ELEMS + PI_ELEMS) ? (qOut + Q_ELEMS)
                                                            : nullptr;

    // 1. pack combined second-layer weights
    {
        int total = EQ * N2;
        pack_w2_kernel<<<(total + 255) / 256, 256>>>(theta_w, theta_b,
                                                     Theta_w, Theta_b);
    }

    // 2. h = gelu(hx @ dense_w + dense_b)
    {
        dim3 grid(EQ / 128, NROWS / 128);
        sgemm_kernel<true><<<grid, 256>>>(hx, dense_w, dense_b, hptr,
                                          NROWS, EQ, EQ);
    }

    // 3. LayerNorm rows in-place
    ln_kernel<<<NROWS, 256>>>(hptr, ln_g, ln_b);

    // 4. logits2 = h @ [theta_w | Theta_w] + bias
    {
        dim3 grid((N2 + 127) / 128, NROWS / 128);
        sgemm_kernel<false><<<grid, 256>>>(hptr, w2ptr, b2ptr, l2ptr,
                                           NROWS, N2, EQ);
    }

    // 5. per-row epilogue -> Q, pi
    finalize_kernel<<<NROWS / 8, dim3(32, 8)>>>(vmask, qOut, piOut);
}

// round 4
// speedup vs baseline: 2.2139x; 2.2139x over previous
#include <cuda_runtime.h>
#include <cuda_bf16.h>
#include <math.h>
#include <stdint.h>

// ---------------------------------------------------------------- constants
#define NROWS 32768          // B*L
#define EQ    1280
#define KDIM  1280
#define VQ    32
#define PQ    496
#define N2P   640            // padded width of second GEMM (528 -> 640)
#define LN_EPS 1e-12f
#define KC    32             // K per chunk
#define NCH   (KDIM / KC)    // 40

// ---------------------------------------------------------------- scratch
__device__ float g_h[(size_t)NROWS * EQ];      // post-GELU / post-LN hidden
__device__ float g_l2[(size_t)NROWS * N2P];    // [pi_logits(32) | Theta(496) | pad]
__device__ __nv_bfloat16 g_w1h[(size_t)EQ * KDIM];   // dense_w^T hi  [n][k]
__device__ __nv_bfloat16 g_w1l[(size_t)EQ * KDIM];   // dense_w^T lo
__device__ __nv_bfloat16 g_w2h[(size_t)N2P * KDIM];  // packed [theta|Theta]^T hi
__device__ __nv_bfloat16 g_w2l[(size_t)N2P * KDIM];  // packed lo
__device__ float g_b2[N2P];

// ---------------------------------------------------------------- PTX utils
__device__ __forceinline__ uint32_t smem_u32(const void* p) {
    uint32_t a;
    asm("{ .reg .u64 t; cvta.to.shared.u64 t, %1; cvt.u32.u64 %0, t; }"
        : "=r"(a) : "l"(p));
    return a;
}

__device__ __forceinline__ void ldsm4(uint32_t* r, uint32_t addr) {
    asm volatile("ldmatrix.sync.aligned.m8n8.x4.shared.b16 {%0,%1,%2,%3}, [%4];"
                 : "=r"(r[0]), "=r"(r[1]), "=r"(r[2]), "=r"(r[3]) : "r"(addr));
}

__device__ __forceinline__ void mma16816(float* d, const uint32_t* a,
                                         const uint32_t* b) {
    asm volatile(
        "mma.sync.aligned.m16n8k16.row.col.f32.bf16.bf16.f32 "
        "{%0,%1,%2,%3}, {%4,%5,%6,%7}, {%8,%9}, {%0,%1,%2,%3};"
        : "+f"(d[0]), "+f"(d[1]), "+f"(d[2]), "+f"(d[3])
        : "r"(a[0]), "r"(a[1]), "r"(a[2]), "r"(a[3]), "r"(b[0]), "r"(b[1]));
}

// ---------------------------------------------------------------- weight prep
// Split fp32 -> (hi = top-16-bit truncation, lo = rn(x - hi)) bf16 pair.
__global__ void split_w1_kernel(const float* __restrict__ w) {
    int idx = blockIdx.x * blockDim.x + threadIdx.x;
    if (idx >= EQ * KDIM) return;
    int n = idx / KDIM;
    int k = idx - n * KDIM;
    float v = w[(size_t)k * EQ + n];
    uint32_t b = __float_as_uint(v);
    float hi = __uint_as_float(b & 0xffff0000u);
    g_w1h[idx] = __ushort_as_bfloat16((unsigned short)(b >> 16));
    g_w1l[idx] = __float2bfloat16(v - hi);
}

__global__ void split_w2_kernel(const float* __restrict__ tw,
                                const float* __restrict__ tb,
                                const float* __restrict__ Tw,
                                const float* __restrict__ Tb) {
    int idx = blockIdx.x * blockDim.x + threadIdx.x;
    if (idx < N2P * KDIM) {
        int n = idx / KDIM;
        int k = idx - n * KDIM;
        float v = 0.0f;
        if (n < VQ)           v = tw[(size_t)k * VQ + n];
        else if (n < VQ + PQ) v = Tw[(size_t)k * PQ + (n - VQ)];
        uint32_t b = __float_as_uint(v);
        float hi = __uint_as_float(b & 0xffff0000u);
        g_w2h[idx] = __ushort_as_bfloat16((unsigned short)(b >> 16));
        g_w2l[idx] = __float2bfloat16(v - hi);
    }
    if (idx < N2P)
        g_b2[idx] = (idx < VQ) ? tb[idx] : (idx < VQ + PQ ? Tb[idx - VQ] : 0.0f);
}

// ---------------------------------------------------------------- GEMM (HMMA)
// C[128 x 128 tile] = A(fp32,[m][k]) @ B^T where B given pre-split bf16 [n][k].
// A is split to bf16 hi/lo on the fly. 3 MMA passes: hh + hl + lh.
// SMEM pieces per stage: Ahi, Alo, Bhi, Blo; 128 rows x 32 bf16, row stride 80B.
template <bool GELU>
__global__ void __launch_bounds__(256, 1)
gemm_mma_kernel(const float* __restrict__ A,
                const __nv_bfloat16* __restrict__ Bhg_,
                const __nv_bfloat16* __restrict__ Blg_,
                const float* __restrict__ bias, float* __restrict__ C,
                int ldc) {
    extern __shared__ char sm[];
    const uint32_t sb = smem_u32(sm);
    constexpr uint32_t RS = 80;           // smem row stride (bytes)
    constexpr uint32_t PIECE = 128 * RS;  // 10240
    constexpr uint32_t STAGE = 4 * PIECE; // 40960

    int tid = threadIdx.x;
    int lane = tid & 31;
    int wid = tid >> 5;
    int wm = (wid & 3) * 32;    // warp m-offset in tile
    int wn = (wid >> 2) * 64;   // warp n-offset in tile
    int m0 = blockIdx.y * 128;
    int n0 = blockIdx.x * 128;

    // loader mapping: thread -> (row, 16-element k-half)
    int lr = tid >> 1;
    int lk = (tid & 1) * 16;
    const float* Ag = A + (size_t)(m0 + lr) * KDIM + lk;
    const __nv_bfloat16* Bhg = Bhg_ + (size_t)(n0 + lr) * KDIM + lk;
    const __nv_bfloat16* Blg = Blg_ + (size_t)(n0 + lr) * KDIM + lk;
    uint32_t sOff = (uint32_t)lr * RS + (uint32_t)lk * 2;

    // ldmatrix per-lane row/k offsets
    int rA = (lane & 7) + ((lane >> 3) & 1) * 8;
    uint32_t kA = (uint32_t)((lane >> 4) & 1) * 16;
    int rB = (lane & 7) + ((lane >> 4) & 1) * 8;
    uint32_t kB = (uint32_t)((lane >> 3) & 1) * 16;

    float acc[2][8][4];
#pragma unroll
    for (int i = 0; i < 2; i++)
#pragma unroll
        for (int j = 0; j < 8; j++)
#pragma unroll
            for (int q = 0; q < 4; q++) acc[i][j][q] = 0.0f;

    float4 pa[4];
    uint4 pbh[2], pbl[2];

    // helper lambdas ------------------------------------------------------
    auto ldg_chunk = [&](int c) {
        const float4* ap = (const float4*)(Ag + (size_t)c * KC);
#pragma unroll
        for (int q = 0; q < 4; q++) pa[q] = ap[q];
        const uint4* bhp = (const uint4*)(Bhg + (size_t)c * KC);
        const uint4* blp = (const uint4*)(Blg + (size_t)c * KC);
        pbh[0] = bhp[0]; pbh[1] = bhp[1];
        pbl[0] = blp[0]; pbl[1] = blp[1];
    };
    auto sts_chunk = [&](int buf) {
        char* dst = sm + (uint32_t)buf * STAGE + sOff;
        uint32_t h[8], l[8];
#pragma unroll
        for (int q = 0; q < 4; q++) {
            uint32_t bx = __float_as_uint(pa[q].x), by = __float_as_uint(pa[q].y);
            uint32_t bz = __float_as_uint(pa[q].z), bw = __float_as_uint(pa[q].w);
            h[2 * q]     = __byte_perm(bx, by, 0x7632);
            h[2 * q + 1] = __byte_perm(bz, bw, 0x7632);
            float lx = pa[q].x - __uint_as_float(bx & 0xffff0000u);
            float ly = pa[q].y - __uint_as_float(by & 0xffff0000u);
            float lz = pa[q].z - __uint_as_float(bz & 0xffff0000u);
            float lw = pa[q].w - __uint_as_float(bw & 0xffff0000u);
            __nv_bfloat162 p01 = __floats2bfloat162_rn(lx, ly);
            __nv_bfloat162 p23 = __floats2bfloat162_rn(lz, lw);
            l[2 * q]     = *(uint32_t*)&p01;
            l[2 * q + 1] = *(uint32_t*)&p23;
        }
        *(uint4*)(dst)              = make_uint4(h[0], h[1], h[2], h[3]);
        *(uint4*)(dst + 16)         = make_uint4(h[4], h[5], h[6], h[7]);
        *(uint4*)(dst + PIECE)      = make_uint4(l[0], l[1], l[2], l[3]);
        *(uint4*)(dst + PIECE + 16) = make_uint4(l[4], l[5], l[6], l[7]);
        *(uint4*)(dst + 2 * PIECE)      = pbh[0];
        *(uint4*)(dst + 2 * PIECE + 16) = pbh[1];
        *(uint4*)(dst + 3 * PIECE)      = pbl[0];
        *(uint4*)(dst + 3 * PIECE + 16) = pbl[1];
    };
    // ----------------------------------------------------------------------

    ldg_chunk(0);
    sts_chunk(0);
    __syncthreads();

    for (int c = 0; c < NCH; c++) {
        int cn = c + 1;
        if (cn < NCH) ldg_chunk(cn);

        uint32_t st = sb + (uint32_t)(c & 1) * STAGE;
#pragma unroll
        for (int ks = 0; ks < 2; ks++) {
            uint32_t kbyte = (uint32_t)ks * 32;
            uint32_t ah[2][4], al[2][4], bh[8][2], bl[8][2];
#pragma unroll
            for (int mf = 0; mf < 2; mf++) {
                uint32_t ad =
                    st + (uint32_t)(wm + mf * 16 + rA) * RS + kbyte + kA;
                ldsm4(ah[mf], ad);
                ldsm4(al[mf], ad + PIECE);
            }
#pragma unroll
            for (int g = 0; g < 4; g++) {
                uint32_t bd = st + 2 * PIECE +
                              (uint32_t)(wn + g * 16 + rB) * RS + kbyte + kB;
                uint32_t t[4];
                ldsm4(t, bd);
                bh[2 * g][0] = t[0]; bh[2 * g][1] = t[1];
                bh[2 * g + 1][0] = t[2]; bh[2 * g + 1][1] = t[3];
                ldsm4(t, bd + PIECE);
                bl[2 * g][0] = t[0]; bl[2 * g][1] = t[1];
                bl[2 * g + 1][0] = t[2]; bl[2 * g + 1][1] = t[3];
            }
#pragma unroll
            for (int mf = 0; mf < 2; mf++)
#pragma unroll
                for (int nf = 0; nf < 8; nf++) {
                    mma16816(acc[mf][nf], ah[mf], bh[nf]);
                    mma16816(acc[mf][nf], ah[mf], bl[nf]);
                    mma16816(acc[mf][nf], al[mf], bh[nf]);
                }
        }

        if (cn < NCH) sts_chunk(cn & 1);
        __syncthreads();
    }

    // epilogue: bias (+ GELU), direct global stores
    int tr = lane >> 2;
    int tc = (lane & 3) * 2;
#pragma unroll
    for (int mf = 0; mf < 2; mf++) {
#pragma unroll
        for (int nf = 0; nf < 8; nf++) {
            int col = n0 + wn + nf * 8 + tc;
            float2 bb = *(const float2*)&bias[col];
            int r1 = m0 + wm + mf * 16 + tr;
#pragma unroll
            for (int h = 0; h < 2; h++) {
                float v0 = acc[mf][nf][2 * h + 0] + bb.x;
                float v1 = acc[mf][nf][2 * h + 1] + bb.y;
                if (GELU) {
                    v0 = 0.5f * v0 * (1.0f + erff(v0 * 0.70710678118654752f));
                    v1 = 0.5f * v1 * (1.0f + erff(v1 * 0.70710678118654752f));
                }
                *(float2*)&C[(size_t)(r1 + 8 * h) * ldc + col] =
                    make_float2(v0, v1);
            }
        }
    }
}

// ---------------------------------------------------------------- LayerNorm
__device__ __forceinline__ float block_reduce_sum(float v) {
    __shared__ float sh[8];
#pragma unroll
    for (int o = 16; o > 0; o >>= 1) v += __shfl_xor_sync(0xffffffffu, v, o);
    int lane = threadIdx.x & 31, wid = threadIdx.x >> 5;
    if (lane == 0) sh[wid] = v;
    __syncthreads();
    v = (lane < 8) ? sh[lane] : 0.0f;
#pragma unroll
    for (int o = 4; o > 0; o >>= 1) v += __shfl_xor_sync(0xffffffffu, v, o);
    v = __shfl_sync(0xffffffffu, v, 0);
    __syncthreads();
    return v;
}

__global__ void ln_kernel(float* __restrict__ h, const float* __restrict__ g,
                          const float* __restrict__ b) {
    size_t r = blockIdx.x;
    float* row = h + r * EQ;
    int t = threadIdx.x;
    float x[5];
    float s = 0.0f;
#pragma unroll
    for (int i = 0; i < 5; i++) { x[i] = row[t + i * 256]; s += x[i]; }
    float mu = block_reduce_sum(s) * (1.0f / EQ);
    float v = 0.0f;
#pragma unroll
    for (int i = 0; i < 5; i++) { float d = x[i] - mu; v += d * d; }
    float var = block_reduce_sum(v) * (1.0f / EQ);
    float inv = rsqrtf(var + LN_EPS);
#pragma unroll
    for (int i = 0; i < 5; i++) {
        int c = t + i * 256;
        row[c] = (x[i] - mu) * inv * g[c] + b[c];
    }
}

// ---------------------------------------------------------------- finalize
__global__ void __launch_bounds__(256)
finalize_kernel(const int* __restrict__ mask32,
                float* __restrict__ qOut, float* __restrict__ piOut) {
    __shared__ float th[8][512];
    __shared__ float psq[8][32];
    __shared__ float mf[32];

    int lane = threadIdx.x;
    int w = threadIdx.y;
    size_t r = (size_t)blockIdx.x * 8 + w;

    if (w == 0) mf[lane] = (mask32[lane] != 0) ? 1.0f : 0.0f;
    __syncthreads();

    const float* base = g_l2 + r * N2P;

    bool mk = mf[lane] > 0.5f;
    float x = base[lane];
    float xm = mk ? x : -INFINITY;
    float mx = xm;
#pragma unroll
    for (int o = 16; o > 0; o >>= 1)
        mx = fmaxf(mx, __shfl_xor_sync(0xffffffffu, mx, o));
    float e = mk ? expf(xm - mx) : 0.0f;
    float ssum = e;
#pragma unroll
    for (int o = 16; o > 0; o >>= 1)
        ssum += __shfl_xor_sync(0xffffffffu, ssum, o);

    if (piOut) piOut[r * VQ + lane] = e / ssum;
    float logpi = xm - mx - logf(ssum);
    psq[w][lane] = mk ? expf(0.5f * logpi) : 1.0f;

    for (int idx = lane; idx < PQ; idx += 32) {
        float t = base[VQ + idx];
        th[w][idx] = fmaxf(t, 0.0f) + log1pf(expf(-fabsf(t)));
    }
    __syncwarp();

    int i = lane;
    float mi = mf[i];
    float inv = 1.0f / psq[w][i];
    float q[32];
    float rs = 0.0f;
#pragma unroll
    for (int j = 0; j < 32; j++) {
        float val = 0.0f;
        if (j != i) {
            int lo = min(i, j), hi = max(i, j);
            int idx = lo * VQ - (lo * (lo + 1)) / 2 + (hi - lo - 1);
            val = th[w][idx] * mi * mf[j] * psq[w][j] * inv;
        }
        q[j] = val;
        rs += val;
    }
#pragma unroll
    for (int j = 0; j < 32; j++)
        if (j == i) q[j] = -rs;

    float* out = qOut + r * (VQ * VQ) + (size_t)i * VQ;
#pragma unroll
    for (int j = 0; j < 32; j += 4)
        *(float4*)(out + j) = make_float4(q[j], q[j + 1], q[j + 2], q[j + 3]);
}

// ---------------------------------------------------------------- launch
extern "C" void kernel_launch(void* const* d_in, const int* in_sizes, int n_in,
                              void* d_out, int out_size) {
    const float* hx      = (const float*)d_in[0];
    const int*   vmask   = (const int*)d_in[1];
    const float* dense_w = (const float*)d_in[2];
    const float* dense_b = (const float*)d_in[3];
    const float* ln_g    = (const float*)d_in[4];
    const float* ln_b    = (const float*)d_in[5];
    const float* theta_w = (const float*)d_in[6];
    const float* theta_b = (const float*)d_in[7];
    const float* Theta_w = (const float*)d_in[8];
    const float* Theta_b = (const float*)d_in[9];

    float *hptr, *l2ptr, *b2ptr;
    __nv_bfloat16 *w1h, *w1l, *w2h, *w2l;
    cudaGetSymbolAddress((void**)&hptr, g_h);
    cudaGetSymbolAddress((void**)&l2ptr, g_l2);
    cudaGetSymbolAddress((void**)&b2ptr, g_b2);
    cudaGetSymbolAddress((void**)&w1h, g_w1h);
    cudaGetSymbolAddress((void**)&w1l, g_w1l);
    cudaGetSymbolAddress((void**)&w2h, g_w2h);
    cudaGetSymbolAddress((void**)&w2l, g_w2l);

    const size_t Q_ELEMS = (size_t)NROWS * VQ * VQ;
    const size_t PI_ELEMS = (size_t)NROWS * VQ;
    float* qOut = (float*)d_out;
    float* piOut = ((size_t)out_size >= Q_ELEMS + PI_ELEMS) ? (qOut + Q_ELEMS)
                                                            : nullptr;

    const int SMEM = 2 * 4 * 128 * 80;   // 81920 bytes
    cudaFuncSetAttribute(gemm_mma_kernel<true>,
                         cudaFuncAttributeMaxDynamicSharedMemorySize, SMEM);
    cudaFuncSetAttribute(gemm_mma_kernel<false>,
                         cudaFuncAttributeMaxDynamicSharedMemorySize, SMEM);

    // 1. split/transpose weights to bf16 hi/lo (K-major)
    split_w1_kernel<<<(EQ * KDIM + 255) / 256, 256>>>(dense_w);
    split_w2_kernel<<<(N2P * KDIM + 255) / 256, 256>>>(theta_w, theta_b,
                                                       Theta_w, Theta_b);

    // 2. h = gelu(hx @ dense_w + dense_b)   [M=32768, N=1280, K=1280]
    {
        dim3 grid(EQ / 128, NROWS / 128);
        gemm_mma_kernel<true><<<grid, 256, SMEM>>>(hx, w1h, w1l, dense_b,
                                                   hptr, EQ);
    }

    // 3. LayerNorm
    ln_kernel<<<NROWS, 256>>>(hptr, ln_g, ln_b);

    // 4. logits2 = h @ [theta|Theta] + bias  [M=32768, N=640, K=1280]
    {
        dim3 grid(N2P / 128, NROWS / 128);
        gemm_mma_kernel<false><<<grid, 256, SMEM>>>(hptr, w2h, w2l, b2ptr,
                                                    l2ptr, N2P);
    }

    // 5. per-row epilogue -> Q, pi
    finalize_kernel<<<NROWS / 8, dim3(32, 8)>>>(vmask, qOut, piOut);
}